// round 16
// baseline (speedup 1.0000x reference)
#include <cuda_runtime.h>
#include <cstdint>

// out_half[h] = X[idx[h], :]  (512B per half-row), h in [0, 2E)
// Persistent blocks, 3-stage SMEM pipeline:
//   stage s: gather 32 half-rows (16KB) via v8 loads -> SMEM,
//            then ONE cp.async.bulk 16KB store (TMA, bypasses L1), no wait.
//   Reuse of stage s only needs wait_group 2 (store from 3 iters ago done).
// Bulk stores drain in background while the next tile is gathered.

#define ROWS_PER_TILE 32
#define TILE_BYTES (ROWS_PER_TILE * 512)   // 16 KB
#define NSTAGE 3
#define GRANS (ROWS_PER_TILE * 16)         // 512 granules (32B) per tile
#define CPT (GRANS / 256)                  // 2 per thread

struct V8 { unsigned r0,r1,r2,r3,r4,r5,r6,r7; };

__device__ __forceinline__ V8 ldg_v8(const void* p) {
    V8 v;
    asm("ld.global.nc.L2::evict_last.v8.b32 {%0,%1,%2,%3,%4,%5,%6,%7}, [%8];"
        : "=r"(v.r0), "=r"(v.r1), "=r"(v.r2), "=r"(v.r3),
          "=r"(v.r4), "=r"(v.r5), "=r"(v.r6), "=r"(v.r7)
        : "l"(p));
    return v;
}

__device__ __forceinline__ void sts_v8(uint32_t a, const V8& v) {
    asm volatile("st.shared.v4.b32 [%0], {%1,%2,%3,%4};"
        :: "r"(a), "r"(v.r0), "r"(v.r1), "r"(v.r2), "r"(v.r3));
    asm volatile("st.shared.v4.b32 [%0], {%1,%2,%3,%4};"
        :: "r"(a + 16), "r"(v.r4), "r"(v.r5), "r"(v.r6), "r"(v.r7));
}

__global__ void __launch_bounds__(256) link_embed_pipe_kernel(
    const char* __restrict__ Xb,
    const int* __restrict__ idx,
    char* __restrict__ outb,
    int H)                             // 2E half-rows
{
    __shared__ __align__(128) char stage[NSTAGE][TILE_BYTES];

    const int tid = threadIdx.x;
    const int full_tiles = H / ROWS_PER_TILE;

    uint32_t sbase;
    asm("{ .reg .u64 t; cvta.to.shared.u64 t, %1; cvt.u32.u64 %0, t; }"
        : "=r"(sbase) : "l"(&stage[0][0]));

    int it = 0;
    for (int tile = blockIdx.x; tile < full_tiles; tile += gridDim.x, ++it) {
        const int s = it % NSTAGE;
        const uint32_t smem = sbase + (unsigned)s * TILE_BYTES;
        const int h0 = tile * ROWS_PER_TILE;

        if (it >= NSTAGE) {
            if (tid == 0)
                asm volatile("cp.async.bulk.wait_group %0;" :: "n"(NSTAGE - 1) : "memory");
            __syncthreads();           // stage s's old store is complete
        }

        // gather 16KB into stage s (v8 loads, 2 in flight per thread)
        unsigned off[CPT];
        #pragma unroll
        for (int i = 0; i < CPT; i++) {
            int g = tid + i * 256;
            int node = __ldg(&idx[h0 + (g >> 4)]);   // 16-lane uniform
            off[i] = ((unsigned)node << 9) | ((unsigned)(g & 15) << 5);
        }
        V8 v[CPT];
        #pragma unroll
        for (int i = 0; i < CPT; i++)
            v[i] = ldg_v8(Xb + off[i]);
        #pragma unroll
        for (int i = 0; i < CPT; i++)
            sts_v8(smem + (unsigned)(tid + i * 256) * 32, v[i]);

        __syncthreads();               // all STS visible

        if (tid == 0) {
            asm volatile("fence.proxy.async.shared::cta;" ::: "memory");
            asm volatile(
                "cp.async.bulk.global.shared::cta.bulk_group [%0], [%1], %2;"
                :: "l"(outb + (size_t)h0 * 512), "r"(smem), "n"(TILE_BYTES)
                : "memory");
            asm volatile("cp.async.bulk.commit_group;" ::: "memory");
            // no wait: store drains while we gather the next tile
        }
    }

    if (tid == 0)
        asm volatile("cp.async.bulk.wait_group 0;" ::: "memory");

    // tail rows (none at bench shape): direct stores
    int tail0 = full_tiles * ROWS_PER_TILE;
    if (blockIdx.x == 0) {
        for (int g = tid; g < (H - tail0) * 16; g += 256) {
            int node = __ldg(&idx[tail0 + (g >> 4)]);
            unsigned off = ((unsigned)node << 9) | ((unsigned)(g & 15) << 5);
            V8 v = ldg_v8(Xb + off);
            uint4* dst = (uint4*)(outb + (size_t)tail0 * 512 + (size_t)g * 32);
            dst[0] = make_uint4(v.r0, v.r1, v.r2, v.r3);
            dst[1] = make_uint4(v.r4, v.r5, v.r6, v.r7);
        }
    }
}

extern "C" void kernel_launch(void* const* d_in, const int* in_sizes, int n_in,
                              void* d_out, int out_size)
{
    const char* Xb = (const char*)d_in[0];
    const int* idx = (const int*)d_in[1];
    char* outb = (char*)d_out;

    int H = in_sizes[1];               // 2E half-rows

    // persistent grid: 4 CTAs/SM (48KB smem each), 148 SMs
    int blocks = 148 * 4;
    int tiles = H / ROWS_PER_TILE;
    if (blocks > tiles && tiles > 0) blocks = tiles;
    if (blocks == 0) blocks = 1;
    link_embed_pipe_kernel<<<blocks, 256>>>(Xb, idx, outb, H);
}